// round 11
// baseline (speedup 1.0000x reference)
#include <cuda_runtime.h>
#include <cuda_fp16.h>
#include <cstdint>

// ---------------- problem constants ----------------
#define NROWS 8192
#define DIN   12544
#define HID   1024

// ---------------- GEMM tile config: 128x128 tile, 4 warps (64x64 warp tile) ----------------
#define BM 128
#define BN 128
#define BK 64
#define ROWB 144                           // 128B data + 16B pad (conflict-free ldmatrix)
#define STAGE_BYTES ((BM + BN) * ROWB)     // 36864
#define SMEM_BYTES (3 * STAGE_BYTES)       // 110592 -> 2 CTAs/SM

// prep kernel sections
#define CONV_BLOCKS 50176                  // 8192*12544/8/256
#define W1T_BX 32
#define W1T_BLOCKS (W1T_BX * (DIN / 32))   // 12544
#define W2T_BX 32
#define W2T_BLOCKS (W2T_BX * (HID / 32))   // 1024
#define PREP_BLOCKS (CONV_BLOCKS + W1T_BLOCKS + W2T_BLOCKS)

// ---------------- device scratch ----------------
__device__ __align__(256) __half g_Xh [(size_t)NROWS * DIN];
__device__ __align__(256) __half g_W1T[(size_t)HID * DIN];
__device__ __align__(256) __half g_W2T[(size_t)HID * HID];
__device__ __align__(256) __half g_H1 [(size_t)NROWS * HID];
__device__ __align__(256) __half g_H2 [(size_t)NROWS * HID];

// ---------------- PTX helpers ----------------
__device__ __forceinline__ uint32_t smem_u32(const void* p) {
    uint32_t a;
    asm("{ .reg .u64 t; cvta.to.shared.u64 t, %1; cvt.u32.u64 %0, t; }" : "=r"(a) : "l"(p));
    return a;
}

#define CP_ASYNC16(dst, src) \
    asm volatile("cp.async.cg.shared.global [%0], [%1], 16;" :: "r"(dst), "l"(src) : "memory")
#define CP_ASYNC_COMMIT() asm volatile("cp.async.commit_group;" ::: "memory")
#define CP_ASYNC_WAIT1()  asm volatile("cp.async.wait_group 1;" ::: "memory")

__device__ __forceinline__ void ldm_x4(uint32_t& r0, uint32_t& r1, uint32_t& r2, uint32_t& r3,
                                       uint32_t addr) {
    asm volatile("ldmatrix.sync.aligned.m8n8.x4.shared.b16 {%0,%1,%2,%3}, [%4];"
                 : "=r"(r0), "=r"(r1), "=r"(r2), "=r"(r3) : "r"(addr));
}

__device__ __forceinline__ void mma16816(float* d, const uint32_t* a, const uint32_t* b) {
    asm volatile(
        "mma.sync.aligned.m16n8k16.row.col.f32.f16.f16.f32 "
        "{%0,%1,%2,%3}, {%4,%5,%6,%7}, {%8,%9}, {%0,%1,%2,%3};"
        : "+f"(d[0]), "+f"(d[1]), "+f"(d[2]), "+f"(d[3])
        : "r"(a[0]), "r"(a[1]), "r"(a[2]), "r"(a[3]), "r"(b[0]), "r"(b[1]));
}

// ---------------- prep: X convert + W1 transpose + W2 transpose, one launch ----------------
__global__ void __launch_bounds__(256) prep_kernel(const float* __restrict__ X, __half* __restrict__ Xh,
                                                   const float* __restrict__ W1, __half* __restrict__ W1T,
                                                   const float* __restrict__ W2, __half* __restrict__ W2T) {
    __shared__ float tile[32][33];
    const int b   = blockIdx.x;
    const int tid = threadIdx.x;

    if (b < CONV_BLOCKS) {
        size_t i = (size_t)b * 256 + tid;
        const float4* p = reinterpret_cast<const float4*>(X) + i * 2;
        float4 a = p[0], c = p[1];
        __half2 h0 = __floats2half2_rn(a.x, a.y), h1 = __floats2half2_rn(a.z, a.w);
        __half2 h2 = __floats2half2_rn(c.x, c.y), h3 = __floats2half2_rn(c.z, c.w);
        uint4 v;
        v.x = *reinterpret_cast<uint32_t*>(&h0);
        v.y = *reinterpret_cast<uint32_t*>(&h1);
        v.z = *reinterpret_cast<uint32_t*>(&h2);
        v.w = *reinterpret_cast<uint32_t*>(&h3);
        reinterpret_cast<uint4*>(Xh)[i] = v;
        return;
    }

    const float* in; __half* out; int R, C, idx, bx;
    if (b < CONV_BLOCKS + W1T_BLOCKS) {
        idx = b - CONV_BLOCKS; in = W1; out = W1T; R = DIN; C = HID; bx = W1T_BX;
    } else {
        idx = b - CONV_BLOCKS - W1T_BLOCKS; in = W2; out = W2T; R = HID; C = HID; bx = W2T_BX;
    }
    const int c0 = (idx % bx) * 32, r0 = (idx / bx) * 32;
    const int x = tid & 31, y = tid >> 5;  // (32, 8)
    #pragma unroll
    for (int j = 0; j < 32; j += 8)
        tile[y + j][x] = in[(size_t)(r0 + y + j) * C + (c0 + x)];
    __syncthreads();
    #pragma unroll
    for (int j = 0; j < 32; j += 8)
        out[(size_t)(c0 + y + j) * R + (r0 + x)] = __float2half_rn(tile[x][y + j]);
}

// ---------------- mma.sync GEMM: 128 threads / 4 warps, warp tile 64x64, 2 CTAs/SM ----------------
// MODE 0: out = half, +bias           (GEMM1 -> H1)
// MODE 1: out = half, relu(+bias)     (GEMM2 -> H2)
template<int MODE>
__global__ void __launch_bounds__(128, 2)
gemm_f16_kernel(const __half* __restrict__ A, const __half* __restrict__ B,
                const float* __restrict__ bias, void* __restrict__ Cout,
                int K, int nk) {
    extern __shared__ char smem[];
    const uint32_t sb = smem_u32(smem);
    const int tid  = threadIdx.x;
    const int wid  = tid >> 5, lane = tid & 31;
    const int wm   = wid & 1;
    const int wn   = wid >> 1;
    const int m0   = blockIdx.y * BM;
    const int n0   = blockIdx.x * BN;

    const int cr = tid >> 3;
    const int cc = (tid & 7) * 16;

    const char* gA = reinterpret_cast<const char*>(A) + ((size_t)(m0 + cr) * K) * 2 + cc;
    const char* gB = reinterpret_cast<const char*>(B) + ((size_t)(n0 + cr) * K) * 2 + cc;
    const size_t rstride = (size_t)16 * K * 2;

    auto issue_stage = [&](int kc, int s) {
        const uint32_t abase = sb + s * STAGE_BYTES;
        const uint32_t bbase = abase + BM * ROWB;
        const size_t koff = (size_t)kc * (BK * 2);
        #pragma unroll
        for (int h = 0; h < 8; h++)
            CP_ASYNC16(abase + (cr + h * 16) * ROWB + cc, gA + koff + h * rstride);
        #pragma unroll
        for (int h = 0; h < 8; h++)
            CP_ASYNC16(bbase + (cr + h * 16) * ROWB + cc, gB + koff + h * rstride);
    };

    const int a_row = lane & 15, a_k8 = lane >> 4;
    const int b_row = (lane & 7) + ((lane >> 4) << 3), b_k8 = (lane >> 3) & 1;

    float acc[4][8][4];
    #pragma unroll
    for (int i = 0; i < 4; i++)
        #pragma unroll
        for (int j = 0; j < 8; j++)
            #pragma unroll
            for (int r = 0; r < 4; r++) acc[i][j][r] = 0.f;

    issue_stage(0, 0); CP_ASYNC_COMMIT();
    if (nk > 1) issue_stage(1, 1); CP_ASYNC_COMMIT();

    int s = 0, s2 = 2;
    for (int kc = 0; kc < nk; kc++) {
        CP_ASYNC_WAIT1();
        __syncthreads();

        if (kc + 2 < nk) issue_stage(kc + 2, s2);
        CP_ASYNC_COMMIT();

        const uint32_t abase = sb + s * STAGE_BYTES;
        const uint32_t bbase = abase + BM * ROWB;

        #pragma unroll
        for (int kk = 0; kk < 4; kk++) {
            uint32_t af[4][4], bf[8][2];
            #pragma unroll
            for (int mi = 0; mi < 4; mi++) {
                uint32_t addr = abase + (wm * 64 + mi * 16 + a_row) * ROWB + (kk * 2 + a_k8) * 16;
                ldm_x4(af[mi][0], af[mi][1], af[mi][2], af[mi][3], addr);
            }
            #pragma unroll
            for (int nb = 0; nb < 4; nb++) {
                uint32_t addr = bbase + (wn * 64 + nb * 16 + b_row) * ROWB + (kk * 2 + b_k8) * 16;
                uint32_t r0, r1, r2, r3;
                ldm_x4(r0, r1, r2, r3, addr);
                bf[nb * 2][0] = r0;     bf[nb * 2][1] = r1;
                bf[nb * 2 + 1][0] = r2; bf[nb * 2 + 1][1] = r3;
            }
            #pragma unroll
            for (int mi = 0; mi < 4; mi++)
                #pragma unroll
                for (int nj = 0; nj < 8; nj++)
                    mma16816(acc[mi][nj], af[mi], bf[nj]);
        }
        s = (s == 2) ? 0 : s + 1;
        s2 = (s2 == 2) ? 0 : s2 + 1;
    }

    const int tq = lane >> 2, tr = lane & 3;
    #pragma unroll
    for (int nj = 0; nj < 8; nj++) {
        const int col = n0 + wn * 64 + nj * 8 + tr * 2;
        const float bx = bias[col], by = bias[col + 1];
        #pragma unroll
        for (int mi = 0; mi < 4; mi++) {
            const int row = m0 + wm * 64 + mi * 16 + tq;
            __half* C = reinterpret_cast<__half*>(Cout);
            if (MODE == 0) {
                __half2 h0 = __floats2half2_rn(acc[mi][nj][0] + bx, acc[mi][nj][1] + by);
                __half2 h1 = __floats2half2_rn(acc[mi][nj][2] + bx, acc[mi][nj][3] + by);
                *reinterpret_cast<__half2*>(C + (size_t)row * HID + col) = h0;
                *reinterpret_cast<__half2*>(C + (size_t)(row + 8) * HID + col) = h1;
            } else {
                __half2 h0 = __floats2half2_rn(fmaxf(acc[mi][nj][0] + bx, 0.f),
                                               fmaxf(acc[mi][nj][1] + by, 0.f));
                __half2 h1 = __floats2half2_rn(fmaxf(acc[mi][nj][2] + bx, 0.f),
                                               fmaxf(acc[mi][nj][3] + by, 0.f));
                *reinterpret_cast<__half2*>(C + (size_t)row * HID + col) = h0;
                *reinterpret_cast<__half2*>(C + (size_t)(row + 8) * HID + col) = h1;
            }
        }
    }
}

// ---------------- heads: 32 rows/block, 8 k-slices/row, weights via L1 ----------------
// thread (r, s): r = tid>>3 (row in block), s = tid&7 (slice).
// slice s covers k = 64*i + 8*s + j  (i=0..15, j=0..7) -> coalesced uint4 H loads.
__global__ void __launch_bounds__(256) heads_kernel(const __half* __restrict__ H,
                                                    const float* __restrict__ Wc, const float* __restrict__ bc,
                                                    const float* __restrict__ Wr, const float* __restrict__ br,
                                                    float* __restrict__ out) {
    const int tid = threadIdx.x;
    const int r   = tid >> 3;          // 0..31
    const int s   = tid & 7;           // 0..7
    const int row = blockIdx.x * 32 + r;

    const uint4*  h4  = reinterpret_cast<const uint4*>(H + (size_t)row * HID);
    const float4* Wc4 = reinterpret_cast<const float4*>(Wc);   // [HID]
    const float4* Wr4 = reinterpret_cast<const float4*>(Wr);   // [HID*3]

    float acc[16];
    #pragma unroll
    for (int o = 0; o < 16; o++) acc[o] = 0.f;

    #pragma unroll 4
    for (int i = 0; i < 16; i++) {
        uint4 hv = h4[8 * i + s];                      // 8 halfs: k = 64i+8s .. +7
        const __half2* hp = reinterpret_cast<const __half2*>(&hv);
        #pragma unroll
        for (int j2 = 0; j2 < 4; j2++) {
            float2 f = __half22float2(hp[j2]);
            const int k0 = 64 * i + 8 * s + 2 * j2;
            #pragma unroll
            for (int t = 0; t < 2; t++) {
                const float hvf = (t == 0) ? f.x : f.y;
                const int k = k0 + t;
                float4 c = __ldg(&Wc4[k]);
                acc[0] += hvf * c.x; acc[1] += hvf * c.y; acc[2] += hvf * c.z; acc[3] += hvf * c.w;
                float4 w0 = __ldg(&Wr4[3 * k]), w1 = __ldg(&Wr4[3 * k + 1]), w2 = __ldg(&Wr4[3 * k + 2]);
                acc[4]  += hvf * w0.x; acc[5]  += hvf * w0.y; acc[6]  += hvf * w0.z; acc[7]  += hvf * w0.w;
                acc[8]  += hvf * w1.x; acc[9]  += hvf * w1.y; acc[10] += hvf * w1.z; acc[11] += hvf * w1.w;
                acc[12] += hvf * w2.x; acc[13] += hvf * w2.y; acc[14] += hvf * w2.z; acc[15] += hvf * w2.w;
            }
        }
    }

    // reduce across the 8 slices (lanes differing in low 3 bits)
    #pragma unroll
    for (int o = 0; o < 16; o++) {
        float v = acc[o];
        v += __shfl_xor_sync(0xffffffffu, v, 4);
        v += __shfl_xor_sync(0xffffffffu, v, 2);
        v += __shfl_xor_sync(0xffffffffu, v, 1);
        acc[o] = v;
    }

    if (s == 0) {
        float res[16];
        #pragma unroll
        for (int o = 0; o < 16; o++)
            res[o] = acc[o] + ((o < 4) ? __ldg(&bc[o]) : __ldg(&br[o - 4]));
        float m = fmaxf(fmaxf(res[0], res[1]), fmaxf(res[2], res[3]));
        float e0 = expf(res[0] - m), e1 = expf(res[1] - m), e2 = expf(res[2] - m), e3 = expf(res[3] - m);
        float inv = 1.f / (e0 + e1 + e2 + e3);
        out[(size_t)row * 4 + 0] = e0 * inv;
        out[(size_t)row * 4 + 1] = e1 * inv;
        out[(size_t)row * 4 + 2] = e2 * inv;
        out[(size_t)row * 4 + 3] = e3 * inv;
        float* box = out + (size_t)NROWS * 4 + (size_t)row * 12;
        #pragma unroll
        for (int o = 0; o < 12; o++) box[o] = res[o + 4];
    }
}

// ---------------- launch (single stream, serial) ----------------
extern "C" void kernel_launch(void* const* d_in, const int* in_sizes, int n_in,
                              void* d_out, int out_size) {
    (void)in_sizes; (void)n_in; (void)out_size;
    const float* X  = (const float*)d_in[0];
    const float* W1 = (const float*)d_in[1];
    const float* b1 = (const float*)d_in[2];
    const float* W2 = (const float*)d_in[3];
    const float* b2 = (const float*)d_in[4];
    const float* Wc = (const float*)d_in[5];
    const float* bc = (const float*)d_in[6];
    const float* Wr = (const float*)d_in[7];
    const float* br = (const float*)d_in[8];
    float* out = (float*)d_out;

    void *pXh, *pW1T, *pW2T, *pH1, *pH2;
    cudaGetSymbolAddress(&pXh,  g_Xh);
    cudaGetSymbolAddress(&pW1T, g_W1T);
    cudaGetSymbolAddress(&pW2T, g_W2T);
    cudaGetSymbolAddress(&pH1,  g_H1);
    cudaGetSymbolAddress(&pH2,  g_H2);

    cudaFuncSetAttribute(gemm_f16_kernel<0>, cudaFuncAttributeMaxDynamicSharedMemorySize, SMEM_BYTES);
    cudaFuncSetAttribute(gemm_f16_kernel<1>, cudaFuncAttributeMaxDynamicSharedMemorySize, SMEM_BYTES);

    // 1) prep: X -> fp16, W1 -> W1T (f16), W2 -> W2T (f16), one launch
    prep_kernel<<<PREP_BLOCKS, 256>>>(X, (__half*)pXh, W1, (__half*)pW1T, W2, (__half*)pW2T);
    // 2) H1 = X @ W1 + b1          (f16 out)
    gemm_f16_kernel<0><<<dim3(HID / BN, NROWS / BM), 128, SMEM_BYTES>>>(
        (const __half*)pXh, (const __half*)pW1T, b1, pH1, DIN, DIN / BK);
    // 3) H2 = relu(H1 @ W2 + b2)   (f16 out)
    gemm_f16_kernel<1><<<dim3(HID / BN, NROWS / BM), 128, SMEM_BYTES>>>(
        (const __half*)pH1, (const __half*)pW2T, b2, pH2, HID, HID / BK);
    // 4) heads (32 rows per block)
    heads_kernel<<<NROWS / 32, 256>>>((const __half*)pH2, Wc, bc, Wr, br, out);
}

// round 12
// speedup vs baseline: 1.1410x; 1.1410x over previous
#include <cuda_runtime.h>
#include <cuda_fp16.h>
#include <cstdint>

// ---------------- problem constants ----------------
#define NROWS 8192
#define DIN   12544
#define HID   1024

// ---------------- GEMM tile config: 128x128 tile, 4 warps (64x64 warp tile) ----------------
#define BM 128
#define BN 128
#define BK 64
#define ROWB 144                           // 128B data + 16B pad (conflict-free ldmatrix)
#define STAGE_BYTES ((BM + BN) * ROWB)     // 36864
#define SMEM_BYTES (3 * STAGE_BYTES)       // 110592 -> 2 CTAs/SM

// prep kernel sections
#define CONV_BLOCKS 50176                  // 8192*12544/8/256
#define W1T_BX 32
#define W1T_BLOCKS (W1T_BX * (DIN / 32))   // 12544
#define W2T_BX 32
#define W2T_BLOCKS (W2T_BX * (HID / 32))   // 1024
#define PREP_BLOCKS (CONV_BLOCKS + W1T_BLOCKS + W2T_BLOCKS)

// ---------------- device scratch ----------------
__device__ __align__(256) __half g_Xh [(size_t)NROWS * DIN];
__device__ __align__(256) __half g_W1T[(size_t)HID * DIN];
__device__ __align__(256) __half g_W2T[(size_t)HID * HID];
__device__ __align__(256) __half g_H1 [(size_t)NROWS * HID];
__device__ __align__(256) __half g_H2 [(size_t)NROWS * HID];

// ---------------- PTX helpers ----------------
__device__ __forceinline__ uint32_t smem_u32(const void* p) {
    uint32_t a;
    asm("{ .reg .u64 t; cvta.to.shared.u64 t, %1; cvt.u32.u64 %0, t; }" : "=r"(a) : "l"(p));
    return a;
}

#define CP_ASYNC16(dst, src) \
    asm volatile("cp.async.cg.shared.global [%0], [%1], 16;" :: "r"(dst), "l"(src) : "memory")
#define CP_ASYNC_COMMIT() asm volatile("cp.async.commit_group;" ::: "memory")
#define CP_ASYNC_WAIT1()  asm volatile("cp.async.wait_group 1;" ::: "memory")

__device__ __forceinline__ void ldm_x4(uint32_t& r0, uint32_t& r1, uint32_t& r2, uint32_t& r3,
                                       uint32_t addr) {
    asm volatile("ldmatrix.sync.aligned.m8n8.x4.shared.b16 {%0,%1,%2,%3}, [%4];"
                 : "=r"(r0), "=r"(r1), "=r"(r2), "=r"(r3) : "r"(addr));
}

__device__ __forceinline__ void mma16816(float* d, const uint32_t* a, const uint32_t* b) {
    asm volatile(
        "mma.sync.aligned.m16n8k16.row.col.f32.f16.f16.f32 "
        "{%0,%1,%2,%3}, {%4,%5,%6,%7}, {%8,%9}, {%0,%1,%2,%3};"
        : "+f"(d[0]), "+f"(d[1]), "+f"(d[2]), "+f"(d[3])
        : "r"(a[0]), "r"(a[1]), "r"(a[2]), "r"(a[3]), "r"(b[0]), "r"(b[1]));
}

// ---------------- prep: X convert + W1 transpose + W2 transpose, one launch ----------------
__global__ void __launch_bounds__(256) prep_kernel(const float* __restrict__ X, __half* __restrict__ Xh,
                                                   const float* __restrict__ W1, __half* __restrict__ W1T,
                                                   const float* __restrict__ W2, __half* __restrict__ W2T) {
    __shared__ float tile[32][33];
    const int b   = blockIdx.x;
    const int tid = threadIdx.x;

    if (b < CONV_BLOCKS) {
        size_t i = (size_t)b * 256 + tid;
        const float4* p = reinterpret_cast<const float4*>(X) + i * 2;
        float4 a = p[0], c = p[1];
        __half2 h0 = __floats2half2_rn(a.x, a.y), h1 = __floats2half2_rn(a.z, a.w);
        __half2 h2 = __floats2half2_rn(c.x, c.y), h3 = __floats2half2_rn(c.z, c.w);
        uint4 v;
        v.x = *reinterpret_cast<uint32_t*>(&h0);
        v.y = *reinterpret_cast<uint32_t*>(&h1);
        v.z = *reinterpret_cast<uint32_t*>(&h2);
        v.w = *reinterpret_cast<uint32_t*>(&h3);
        reinterpret_cast<uint4*>(Xh)[i] = v;
        return;
    }

    const float* in; __half* out; int R, C, idx, bx;
    if (b < CONV_BLOCKS + W1T_BLOCKS) {
        idx = b - CONV_BLOCKS; in = W1; out = W1T; R = DIN; C = HID; bx = W1T_BX;
    } else {
        idx = b - CONV_BLOCKS - W1T_BLOCKS; in = W2; out = W2T; R = HID; C = HID; bx = W2T_BX;
    }
    const int c0 = (idx % bx) * 32, r0 = (idx / bx) * 32;
    const int x = tid & 31, y = tid >> 5;  // (32, 8)
    #pragma unroll
    for (int j = 0; j < 32; j += 8)
        tile[y + j][x] = in[(size_t)(r0 + y + j) * C + (c0 + x)];
    __syncthreads();
    #pragma unroll
    for (int j = 0; j < 32; j += 8)
        out[(size_t)(c0 + y + j) * R + (r0 + x)] = __float2half_rn(tile[x][y + j]);
}

// ---------------- mma.sync GEMM: 128 threads / 4 warps, warp tile 64x64, 2 CTAs/SM ----------------
// MODE 0: out = half, +bias           (GEMM1 -> H1)
// MODE 1: out = half, relu(+bias)     (GEMM2 -> H2)
template<int MODE>
__global__ void __launch_bounds__(128, 2)
gemm_f16_kernel(const __half* __restrict__ A, const __half* __restrict__ B,
                const float* __restrict__ bias, void* __restrict__ Cout,
                int K, int nk) {
    extern __shared__ char smem[];
    const uint32_t sb = smem_u32(smem);
    const int tid  = threadIdx.x;
    const int wid  = tid >> 5, lane = tid & 31;
    const int wm   = wid & 1;
    const int wn   = wid >> 1;
    const int m0   = blockIdx.y * BM;
    const int n0   = blockIdx.x * BN;

    const int cr = tid >> 3;
    const int cc = (tid & 7) * 16;

    const char* gA = reinterpret_cast<const char*>(A) + ((size_t)(m0 + cr) * K) * 2 + cc;
    const char* gB = reinterpret_cast<const char*>(B) + ((size_t)(n0 + cr) * K) * 2 + cc;
    const size_t rstride = (size_t)16 * K * 2;

    auto issue_stage = [&](int kc, int s) {
        const uint32_t abase = sb + s * STAGE_BYTES;
        const uint32_t bbase = abase + BM * ROWB;
        const size_t koff = (size_t)kc * (BK * 2);
        #pragma unroll
        for (int h = 0; h < 8; h++)
            CP_ASYNC16(abase + (cr + h * 16) * ROWB + cc, gA + koff + h * rstride);
        #pragma unroll
        for (int h = 0; h < 8; h++)
            CP_ASYNC16(bbase + (cr + h * 16) * ROWB + cc, gB + koff + h * rstride);
    };

    const int a_row = lane & 15, a_k8 = lane >> 4;
    const int b_row = (lane & 7) + ((lane >> 4) << 3), b_k8 = (lane >> 3) & 1;

    float acc[4][8][4];
    #pragma unroll
    for (int i = 0; i < 4; i++)
        #pragma unroll
        for (int j = 0; j < 8; j++)
            #pragma unroll
            for (int r = 0; r < 4; r++) acc[i][j][r] = 0.f;

    issue_stage(0, 0); CP_ASYNC_COMMIT();
    if (nk > 1) issue_stage(1, 1); CP_ASYNC_COMMIT();

    int s = 0, s2 = 2;
    for (int kc = 0; kc < nk; kc++) {
        CP_ASYNC_WAIT1();
        __syncthreads();

        if (kc + 2 < nk) issue_stage(kc + 2, s2);
        CP_ASYNC_COMMIT();

        const uint32_t abase = sb + s * STAGE_BYTES;
        const uint32_t bbase = abase + BM * ROWB;

        #pragma unroll
        for (int kk = 0; kk < 4; kk++) {
            uint32_t af[4][4], bf[8][2];
            #pragma unroll
            for (int mi = 0; mi < 4; mi++) {
                uint32_t addr = abase + (wm * 64 + mi * 16 + a_row) * ROWB + (kk * 2 + a_k8) * 16;
                ldm_x4(af[mi][0], af[mi][1], af[mi][2], af[mi][3], addr);
            }
            #pragma unroll
            for (int nb = 0; nb < 4; nb++) {
                uint32_t addr = bbase + (wn * 64 + nb * 16 + b_row) * ROWB + (kk * 2 + b_k8) * 16;
                uint32_t r0, r1, r2, r3;
                ldm_x4(r0, r1, r2, r3, addr);
                bf[nb * 2][0] = r0;     bf[nb * 2][1] = r1;
                bf[nb * 2 + 1][0] = r2; bf[nb * 2 + 1][1] = r3;
            }
            #pragma unroll
            for (int mi = 0; mi < 4; mi++)
                #pragma unroll
                for (int nj = 0; nj < 8; nj++)
                    mma16816(acc[mi][nj], af[mi], bf[nj]);
        }
        s = (s == 2) ? 0 : s + 1;
        s2 = (s2 == 2) ? 0 : s2 + 1;
    }

    const int tq = lane >> 2, tr = lane & 3;
    #pragma unroll
    for (int nj = 0; nj < 8; nj++) {
        const int col = n0 + wn * 64 + nj * 8 + tr * 2;
        const float bx = bias[col], by = bias[col + 1];
        #pragma unroll
        for (int mi = 0; mi < 4; mi++) {
            const int row = m0 + wm * 64 + mi * 16 + tq;
            __half* C = reinterpret_cast<__half*>(Cout);
            if (MODE == 0) {
                __half2 h0 = __floats2half2_rn(acc[mi][nj][0] + bx, acc[mi][nj][1] + by);
                __half2 h1 = __floats2half2_rn(acc[mi][nj][2] + bx, acc[mi][nj][3] + by);
                *reinterpret_cast<__half2*>(C + (size_t)row * HID + col) = h0;
                *reinterpret_cast<__half2*>(C + (size_t)(row + 8) * HID + col) = h1;
            } else {
                __half2 h0 = __floats2half2_rn(fmaxf(acc[mi][nj][0] + bx, 0.f),
                                               fmaxf(acc[mi][nj][1] + by, 0.f));
                __half2 h1 = __floats2half2_rn(fmaxf(acc[mi][nj][2] + bx, 0.f),
                                               fmaxf(acc[mi][nj][3] + by, 0.f));
                *reinterpret_cast<__half2*>(C + (size_t)row * HID + col) = h0;
                *reinterpret_cast<__half2*>(C + (size_t)(row + 8) * HID + col) = h1;
            }
        }
    }
}

// ---------------- heads: 4 rows/block, 128 threads, coalesced weights, 4-row register reuse ----------------
// Thread covers k = 128*i + tid (i=0..7): warp reads 32 consecutive float4 weights
// (minimal wavefronts) and reuses each for 4 rows held in registers.
__global__ void __launch_bounds__(128) heads_kernel(const __half* __restrict__ H,
                                                    const float* __restrict__ Wc, const float* __restrict__ bc,
                                                    const float* __restrict__ Wr, const float* __restrict__ br,
                                                    float* __restrict__ out) {
    __shared__ float red[16][64];
    __shared__ float res[4][16];
    const int tid = threadIdx.x, lane = tid & 31, w = tid >> 5;
    const int row0 = blockIdx.x * 4;

    const __half*  hb  = H + (size_t)row0 * HID;
    const float4* Wc4 = reinterpret_cast<const float4*>(Wc);   // [HID]
    const float4* Wr4 = reinterpret_cast<const float4*>(Wr);   // [HID*3]

    float acc[4][16];
    #pragma unroll
    for (int r = 0; r < 4; r++)
        #pragma unroll
        for (int o = 0; o < 16; o++) acc[r][o] = 0.f;

    #pragma unroll 2
    for (int i = 0; i < 8; i++) {
        const int k = i * 128 + tid;
        float4 c  = __ldg(Wc4 + k);
        float4 w0 = __ldg(Wr4 + 3 * k);
        float4 w1 = __ldg(Wr4 + 3 * k + 1);
        float4 w2 = __ldg(Wr4 + 3 * k + 2);
        float hv[4];
        #pragma unroll
        for (int r = 0; r < 4; r++) hv[r] = __half2float(hb[(size_t)r * HID + k]);
        #pragma unroll
        for (int r = 0; r < 4; r++) {
            const float v = hv[r];
            acc[r][0]  += v * c.x;  acc[r][1]  += v * c.y;  acc[r][2]  += v * c.z;  acc[r][3]  += v * c.w;
            acc[r][4]  += v * w0.x; acc[r][5]  += v * w0.y; acc[r][6]  += v * w0.z; acc[r][7]  += v * w0.w;
            acc[r][8]  += v * w1.x; acc[r][9]  += v * w1.y; acc[r][10] += v * w1.z; acc[r][11] += v * w1.w;
            acc[r][12] += v * w2.x; acc[r][13] += v * w2.y; acc[r][14] += v * w2.z; acc[r][15] += v * w2.w;
        }
    }

    // reduce over 8-lane groups (3 shfl levels), then 16 group-partials via smem
    #pragma unroll
    for (int r = 0; r < 4; r++)
        #pragma unroll
        for (int o = 0; o < 16; o++) {
            float v = acc[r][o];
            v += __shfl_xor_sync(0xffffffffu, v, 1);
            v += __shfl_xor_sync(0xffffffffu, v, 2);
            v += __shfl_xor_sync(0xffffffffu, v, 4);
            acc[r][o] = v;
        }
    if ((lane & 7) == 0) {
        const int g = w * 4 + (lane >> 3);
        #pragma unroll
        for (int r = 0; r < 4; r++)
            #pragma unroll
            for (int o = 0; o < 16; o++)
                red[g][r * 16 + o] = acc[r][o];
    }
    __syncthreads();

    if (tid < 64) {
        float v = 0.f;
        #pragma unroll
        for (int j = 0; j < 16; j++) v += red[j][tid];
        const int o = tid & 15;
        v += (o < 4) ? __ldg(&bc[o]) : __ldg(&br[o - 4]);
        res[tid >> 4][o] = v;
    }
    __syncthreads();

    if (tid < 4) {
        const int row = row0 + tid;
        const float l0 = res[tid][0], l1 = res[tid][1], l2 = res[tid][2], l3 = res[tid][3];
        float m = fmaxf(fmaxf(l0, l1), fmaxf(l2, l3));
        float e0 = expf(l0 - m), e1 = expf(l1 - m), e2 = expf(l2 - m), e3 = expf(l3 - m);
        float inv = 1.f / (e0 + e1 + e2 + e3);
        out[(size_t)row * 4 + 0] = e0 * inv;
        out[(size_t)row * 4 + 1] = e1 * inv;
        out[(size_t)row * 4 + 2] = e2 * inv;
        out[(size_t)row * 4 + 3] = e3 * inv;
        float* box = out + (size_t)NROWS * 4 + (size_t)row * 12;
        #pragma unroll
        for (int o = 0; o < 12; o++) box[o] = res[tid][o + 4];
    }
}

// ---------------- launch (single stream, serial) ----------------
extern "C" void kernel_launch(void* const* d_in, const int* in_sizes, int n_in,
                              void* d_out, int out_size) {
    (void)in_sizes; (void)n_in; (void)out_size;
    const float* X  = (const float*)d_in[0];
    const float* W1 = (const float*)d_in[1];
    const float* b1 = (const float*)d_in[2];
    const float* W2 = (const float*)d_in[3];
    const float* b2 = (const float*)d_in[4];
    const float* Wc = (const float*)d_in[5];
    const float* bc = (const float*)d_in[6];
    const float* Wr = (const float*)d_in[7];
    const float* br = (const float*)d_in[8];
    float* out = (float*)d_out;

    void *pXh, *pW1T, *pW2T, *pH1, *pH2;
    cudaGetSymbolAddress(&pXh,  g_Xh);
    cudaGetSymbolAddress(&pW1T, g_W1T);
    cudaGetSymbolAddress(&pW2T, g_W2T);
    cudaGetSymbolAddress(&pH1,  g_H1);
    cudaGetSymbolAddress(&pH2,  g_H2);

    cudaFuncSetAttribute(gemm_f16_kernel<0>, cudaFuncAttributeMaxDynamicSharedMemorySize, SMEM_BYTES);
    cudaFuncSetAttribute(gemm_f16_kernel<1>, cudaFuncAttributeMaxDynamicSharedMemorySize, SMEM_BYTES);

    // 1) prep: X -> fp16, W1 -> W1T (f16), W2 -> W2T (f16), one launch
    prep_kernel<<<PREP_BLOCKS, 256>>>(X, (__half*)pXh, W1, (__half*)pW1T, W2, (__half*)pW2T);
    // 2) H1 = X @ W1 + b1          (f16 out)
    gemm_f16_kernel<0><<<dim3(HID / BN, NROWS / BM), 128, SMEM_BYTES>>>(
        (const __half*)pXh, (const __half*)pW1T, b1, pH1, DIN, DIN / BK);
    // 3) H2 = relu(H1 @ W2 + b2)   (f16 out)
    gemm_f16_kernel<1><<<dim3(HID / BN, NROWS / BM), 128, SMEM_BYTES>>>(
        (const __half*)pH1, (const __half*)pW2T, b2, pH2, HID, HID / BK);
    // 4) heads (4 rows per block, 2048 blocks)
    heads_kernel<<<NROWS / 4, 128>>>((const __half*)pH2, Wc, bc, Wr, br, out);
}

// round 13
// speedup vs baseline: 1.1542x; 1.0116x over previous
#include <cuda_runtime.h>
#include <cuda_fp16.h>
#include <cstdint>

// ---------------- problem constants ----------------
#define NROWS 8192
#define DIN   12544
#define HID   1024

// ---------------- GEMM tile config: 128x128 tile, 4 warps (64x64 warp tile) ----------------
#define BM 128
#define BN 128
#define BK 64
#define ROWB 144                           // 128B data + 16B pad (conflict-free ldmatrix)
#define STAGE_BYTES ((BM + BN) * ROWB)     // 36864
#define SMEM_BYTES (3 * STAGE_BYTES)       // 110592 -> 2 CTAs/SM

// fused-epilogue smem layout (within the same dynamic smem, after mainloop)
#define TILE_PITCH 264                     // 128 halfs (256B) + 8B pad -> 2-way LDS max
#define WSM_OFF    34048                   // 128*264 = 33792, round up
// weights: 128 cols x 16 f32 = 8192 B   (fits: 34048+8192 < 110592)

// prep kernel sections
#define CONV_BLOCKS 50176                  // 8192*12544/8/256
#define W1T_BX 32
#define W1T_BLOCKS (W1T_BX * (DIN / 32))   // 12544
#define W2T_BX 32
#define W2T_BLOCKS (W2T_BX * (HID / 32))   // 1024
#define ZERO_BLOCKS 128                    // 8192*16 f32 = 512KB = 128*256*16B
#define PREP_BLOCKS (CONV_BLOCKS + W1T_BLOCKS + W2T_BLOCKS + ZERO_BLOCKS)

// ---------------- device scratch ----------------
__device__ __align__(256) __half g_Xh [(size_t)NROWS * DIN];
__device__ __align__(256) __half g_W1T[(size_t)HID * DIN];
__device__ __align__(256) __half g_W2T[(size_t)HID * HID];
__device__ __align__(256) __half g_H1 [(size_t)NROWS * HID];
__device__ __align__(256) float  g_HS [(size_t)NROWS * 16];   // head partial sums

// ---------------- PTX helpers ----------------
__device__ __forceinline__ uint32_t smem_u32(const void* p) {
    uint32_t a;
    asm("{ .reg .u64 t; cvta.to.shared.u64 t, %1; cvt.u32.u64 %0, t; }" : "=r"(a) : "l"(p));
    return a;
}

#define CP_ASYNC16(dst, src) \
    asm volatile("cp.async.cg.shared.global [%0], [%1], 16;" :: "r"(dst), "l"(src) : "memory")
#define CP_ASYNC_COMMIT() asm volatile("cp.async.commit_group;" ::: "memory")
#define CP_ASYNC_WAIT1()  asm volatile("cp.async.wait_group 1;" ::: "memory")

__device__ __forceinline__ void ldm_x4(uint32_t& r0, uint32_t& r1, uint32_t& r2, uint32_t& r3,
                                       uint32_t addr) {
    asm volatile("ldmatrix.sync.aligned.m8n8.x4.shared.b16 {%0,%1,%2,%3}, [%4];"
                 : "=r"(r0), "=r"(r1), "=r"(r2), "=r"(r3) : "r"(addr));
}

__device__ __forceinline__ void mma16816(float* d, const uint32_t* a, const uint32_t* b) {
    asm volatile(
        "mma.sync.aligned.m16n8k16.row.col.f32.f16.f16.f32 "
        "{%0,%1,%2,%3}, {%4,%5,%6,%7}, {%8,%9}, {%0,%1,%2,%3};"
        : "+f"(d[0]), "+f"(d[1]), "+f"(d[2]), "+f"(d[3])
        : "r"(a[0]), "r"(a[1]), "r"(a[2]), "r"(a[3]), "r"(b[0]), "r"(b[1]));
}

// ---------------- prep: X convert + W1/W2 transpose + g_HS zero, one launch ----------------
__global__ void __launch_bounds__(256) prep_kernel(const float* __restrict__ X, __half* __restrict__ Xh,
                                                   const float* __restrict__ W1, __half* __restrict__ W1T,
                                                   const float* __restrict__ W2, __half* __restrict__ W2T,
                                                   float* __restrict__ HS) {
    __shared__ float tile[32][33];
    const int b   = blockIdx.x;
    const int tid = threadIdx.x;

    if (b < CONV_BLOCKS) {
        size_t i = (size_t)b * 256 + tid;
        const float4* p = reinterpret_cast<const float4*>(X) + i * 2;
        float4 a = p[0], c = p[1];
        __half2 h0 = __floats2half2_rn(a.x, a.y), h1 = __floats2half2_rn(a.z, a.w);
        __half2 h2 = __floats2half2_rn(c.x, c.y), h3 = __floats2half2_rn(c.z, c.w);
        uint4 v;
        v.x = *reinterpret_cast<uint32_t*>(&h0);
        v.y = *reinterpret_cast<uint32_t*>(&h1);
        v.z = *reinterpret_cast<uint32_t*>(&h2);
        v.w = *reinterpret_cast<uint32_t*>(&h3);
        reinterpret_cast<uint4*>(Xh)[i] = v;
        return;
    }
    if (b >= CONV_BLOCKS + W1T_BLOCKS + W2T_BLOCKS) {
        // zero head staging
        size_t i = (size_t)(b - CONV_BLOCKS - W1T_BLOCKS - W2T_BLOCKS) * 256 + tid;
        reinterpret_cast<uint4*>(HS)[i] = make_uint4(0, 0, 0, 0);
        return;
    }

    const float* in; __half* out; int R, C, idx, bx;
    if (b < CONV_BLOCKS + W1T_BLOCKS) {
        idx = b - CONV_BLOCKS; in = W1; out = W1T; R = DIN; C = HID; bx = W1T_BX;
    } else {
        idx = b - CONV_BLOCKS - W1T_BLOCKS; in = W2; out = W2T; R = HID; C = HID; bx = W2T_BX;
    }
    const int c0 = (idx % bx) * 32, r0 = (idx / bx) * 32;
    const int x = tid & 31, y = tid >> 5;
    #pragma unroll
    for (int j = 0; j < 32; j += 8)
        tile[y + j][x] = in[(size_t)(r0 + y + j) * C + (c0 + x)];
    __syncthreads();
    #pragma unroll
    for (int j = 0; j < 32; j += 8)
        out[(size_t)(c0 + y + j) * R + (r0 + x)] = __float2half_rn(tile[x][y + j]);
}

// ---------------- mma.sync GEMM: 128 threads / 4 warps, warp tile 64x64, 2 CTAs/SM ----------------
// MODE 0: C = half* H1, epilogue = +bias, f16 store.
// MODE 1: C = float* g_HS; epilogue = relu(+bias) -> smem tile -> per-row head
//         partials vs Wc/Wr (staged in smem) -> atomicAdd into g_HS. No H2.
template<int MODE>
__global__ void __launch_bounds__(128, 2)
gemm_f16_kernel(const __half* __restrict__ A, const __half* __restrict__ B,
                const float* __restrict__ bias, void* __restrict__ Cout,
                const float* __restrict__ WcH, const float* __restrict__ WrH,
                int K, int nk) {
    extern __shared__ char smem[];
    const uint32_t sb = smem_u32(smem);
    const int tid  = threadIdx.x;
    const int wid  = tid >> 5, lane = tid & 31;
    const int wm   = wid & 1;
    const int wn   = wid >> 1;
    const int m0   = blockIdx.y * BM;
    const int n0   = blockIdx.x * BN;

    const int cr = tid >> 3;
    const int cc = (tid & 7) * 16;

    const char* gA = reinterpret_cast<const char*>(A) + ((size_t)(m0 + cr) * K) * 2 + cc;
    const char* gB = reinterpret_cast<const char*>(B) + ((size_t)(n0 + cr) * K) * 2 + cc;
    const size_t rstride = (size_t)16 * K * 2;

    auto issue_stage = [&](int kc, int s) {
        const uint32_t abase = sb + s * STAGE_BYTES;
        const uint32_t bbase = abase + BM * ROWB;
        const size_t koff = (size_t)kc * (BK * 2);
        #pragma unroll
        for (int h = 0; h < 8; h++)
            CP_ASYNC16(abase + (cr + h * 16) * ROWB + cc, gA + koff + h * rstride);
        #pragma unroll
        for (int h = 0; h < 8; h++)
            CP_ASYNC16(bbase + (cr + h * 16) * ROWB + cc, gB + koff + h * rstride);
    };

    const int a_row = lane & 15, a_k8 = lane >> 4;
    const int b_row = (lane & 7) + ((lane >> 4) << 3), b_k8 = (lane >> 3) & 1;

    float acc[4][8][4];
    #pragma unroll
    for (int i = 0; i < 4; i++)
        #pragma unroll
        for (int j = 0; j < 8; j++)
            #pragma unroll
            for (int r = 0; r < 4; r++) acc[i][j][r] = 0.f;

    issue_stage(0, 0); CP_ASYNC_COMMIT();
    if (nk > 1) issue_stage(1, 1); CP_ASYNC_COMMIT();

    int s = 0, s2 = 2;
    for (int kc = 0; kc < nk; kc++) {
        CP_ASYNC_WAIT1();
        __syncthreads();

        if (kc + 2 < nk) issue_stage(kc + 2, s2);
        CP_ASYNC_COMMIT();

        const uint32_t abase = sb + s * STAGE_BYTES;
        const uint32_t bbase = abase + BM * ROWB;

        #pragma unroll
        for (int kk = 0; kk < 4; kk++) {
            uint32_t af[4][4], bf[8][2];
            #pragma unroll
            for (int mi = 0; mi < 4; mi++) {
                uint32_t addr = abase + (wm * 64 + mi * 16 + a_row) * ROWB + (kk * 2 + a_k8) * 16;
                ldm_x4(af[mi][0], af[mi][1], af[mi][2], af[mi][3], addr);
            }
            #pragma unroll
            for (int nb = 0; nb < 4; nb++) {
                uint32_t addr = bbase + (wn * 64 + nb * 16 + b_row) * ROWB + (kk * 2 + b_k8) * 16;
                uint32_t r0, r1, r2, r3;
                ldm_x4(r0, r1, r2, r3, addr);
                bf[nb * 2][0] = r0;     bf[nb * 2][1] = r1;
                bf[nb * 2 + 1][0] = r2; bf[nb * 2 + 1][1] = r3;
            }
            #pragma unroll
            for (int mi = 0; mi < 4; mi++)
                #pragma unroll
                for (int nj = 0; nj < 8; nj++)
                    mma16816(acc[mi][nj], af[mi], bf[nj]);
        }
        s = (s == 2) ? 0 : s + 1;
        s2 = (s2 == 2) ? 0 : s2 + 1;
    }

    const int tq = lane >> 2, tr = lane & 3;

    if (MODE == 0) {
        __half* C = reinterpret_cast<__half*>(Cout);
        #pragma unroll
        for (int nj = 0; nj < 8; nj++) {
            const int col = n0 + wn * 64 + nj * 8 + tr * 2;
            const float bx = bias[col], by = bias[col + 1];
            #pragma unroll
            for (int mi = 0; mi < 4; mi++) {
                const int row = m0 + wm * 64 + mi * 16 + tq;
                __half2 h0 = __floats2half2_rn(acc[mi][nj][0] + bx, acc[mi][nj][1] + by);
                __half2 h1 = __floats2half2_rn(acc[mi][nj][2] + bx, acc[mi][nj][3] + by);
                *reinterpret_cast<__half2*>(C + (size_t)row * HID + col) = h0;
                *reinterpret_cast<__half2*>(C + (size_t)(row + 8) * HID + col) = h1;
            }
        }
        return;
    }

    // ================= MODE 1: fused relu + head partials =================
    __syncthreads();   // all warps done with pipeline smem

    // 1) store relu'd h tile (f16) into smem: addr = rowl*TILE_PITCH + coll*2
    #pragma unroll
    for (int nj = 0; nj < 8; nj++) {
        const int coll = wn * 64 + nj * 8 + tr * 2;
        const float bx = bias[n0 + coll], by = bias[n0 + coll + 1];
        #pragma unroll
        for (int mi = 0; mi < 4; mi++) {
            const int rowl = wm * 64 + mi * 16 + tq;
            __half2 h0 = __floats2half2_rn(fmaxf(acc[mi][nj][0] + bx, 0.f),
                                           fmaxf(acc[mi][nj][1] + by, 0.f));
            __half2 h1 = __floats2half2_rn(fmaxf(acc[mi][nj][2] + bx, 0.f),
                                           fmaxf(acc[mi][nj][3] + by, 0.f));
            *reinterpret_cast<__half2*>(smem + rowl * TILE_PITCH + coll * 2) = h0;
            *reinterpret_cast<__half2*>(smem + (rowl + 8) * TILE_PITCH + coll * 2) = h1;
        }
    }

    // 2) stage head weights for this block's 128 cols: wsm[c][0..15]
    {
        const int c = tid;                       // 0..127
        const int col = n0 + c;
        const float4* Wc4 = reinterpret_cast<const float4*>(WcH);
        const float4* Wr4 = reinterpret_cast<const float4*>(WrH);
        float4* w = reinterpret_cast<float4*>(smem + WSM_OFF + c * 64);
        w[0] = __ldg(Wc4 + col);
        w[1] = __ldg(Wr4 + 3 * col);
        w[2] = __ldg(Wr4 + 3 * col + 1);
        w[3] = __ldg(Wr4 + 3 * col + 2);
    }
    __syncthreads();

    // 3) thread t = local row: po[16] over this block's 128 cols
    {
        float po[16];
        #pragma unroll
        for (int o = 0; o < 16; o++) po[o] = 0.f;
        const char* trow = smem + tid * TILE_PITCH;
        #pragma unroll 4
        for (int j = 0; j < 32; j++) {           // 4 cols per step
            uint2 hv = *reinterpret_cast<const uint2*>(trow + j * 8);
            const __half2* hp = reinterpret_cast<const __half2*>(&hv);
            float2 f0 = __half22float2(hp[0]), f1 = __half22float2(hp[1]);
            float hvv[4] = { f0.x, f0.y, f1.x, f1.y };
            #pragma unroll
            for (int q = 0; q < 4; q++) {
                const float v = hvv[q];
                const float4* w = reinterpret_cast<const float4*>(smem + WSM_OFF + (4 * j + q) * 64);
                float4 a = w[0], b2 = w[1], c2 = w[2], d = w[3];
                po[0]  += v * a.x;  po[1]  += v * a.y;  po[2]  += v * a.z;  po[3]  += v * a.w;
                po[4]  += v * b2.x; po[5]  += v * b2.y; po[6]  += v * b2.z; po[7]  += v * b2.w;
                po[8]  += v * c2.x; po[9]  += v * c2.y; po[10] += v * c2.z; po[11] += v * c2.w;
                po[12] += v * d.x;  po[13] += v * d.y;  po[14] += v * d.z;  po[15] += v * d.w;
            }
        }
        float* gs = reinterpret_cast<float*>(Cout) + (size_t)(m0 + tid) * 16;
        #pragma unroll
        for (int o = 0; o < 16; o++) atomicAdd(gs + o, po[o]);
    }
}

// ---------------- finalize: bias + softmax + box stores ----------------
__global__ void __launch_bounds__(256) finalize_kernel(const float* __restrict__ HS,
                                                       const float* __restrict__ bc,
                                                       const float* __restrict__ br,
                                                       float* __restrict__ out) {
    const int row = blockIdx.x * 256 + threadIdx.x;
    const float4* p = reinterpret_cast<const float4*>(HS + (size_t)row * 16);
    float4 v0 = p[0], v1 = p[1], v2 = p[2], v3 = p[3];
    float res[16] = { v0.x, v0.y, v0.z, v0.w, v1.x, v1.y, v1.z, v1.w,
                      v2.x, v2.y, v2.z, v2.w, v3.x, v3.y, v3.z, v3.w };
    #pragma unroll
    for (int o = 0; o < 16; o++)
        res[o] += (o < 4) ? __ldg(&bc[o]) : __ldg(&br[o - 4]);
    float m = fmaxf(fmaxf(res[0], res[1]), fmaxf(res[2], res[3]));
    float e0 = expf(res[0] - m), e1 = expf(res[1] - m), e2 = expf(res[2] - m), e3 = expf(res[3] - m);
    float inv = 1.f / (e0 + e1 + e2 + e3);
    out[(size_t)row * 4 + 0] = e0 * inv;
    out[(size_t)row * 4 + 1] = e1 * inv;
    out[(size_t)row * 4 + 2] = e2 * inv;
    out[(size_t)row * 4 + 3] = e3 * inv;
    float* box = out + (size_t)NROWS * 4 + (size_t)row * 12;
    #pragma unroll
    for (int o = 0; o < 12; o++) box[o] = res[o + 4];
}

// ---------------- launch (single stream, serial) ----------------
extern "C" void kernel_launch(void* const* d_in, const int* in_sizes, int n_in,
                              void* d_out, int out_size) {
    (void)in_sizes; (void)n_in; (void)out_size;
    const float* X  = (const float*)d_in[0];
    const float* W1 = (const float*)d_in[1];
    const float* b1 = (const float*)d_in[2];
    const float* W2 = (const float*)d_in[3];
    const float* b2 = (const float*)d_in[4];
    const float* Wc = (const float*)d_in[5];
    const float* bc = (const float*)d_in[6];
    const float* Wr = (const float*)d_in[7];
    const float* br = (const float*)d_in[8];
    float* out = (float*)d_out;

    void *pXh, *pW1T, *pW2T, *pH1, *pHS;
    cudaGetSymbolAddress(&pXh,  g_Xh);
    cudaGetSymbolAddress(&pW1T, g_W1T);
    cudaGetSymbolAddress(&pW2T, g_W2T);
    cudaGetSymbolAddress(&pH1,  g_H1);
    cudaGetSymbolAddress(&pHS,  g_HS);

    cudaFuncSetAttribute(gemm_f16_kernel<0>, cudaFuncAttributeMaxDynamicSharedMemorySize, SMEM_BYTES);
    cudaFuncSetAttribute(gemm_f16_kernel<1>, cudaFuncAttributeMaxDynamicSharedMemorySize, SMEM_BYTES);

    // 1) prep: X -> fp16, W1/W2 transposed f16, zero head staging
    prep_kernel<<<PREP_BLOCKS, 256>>>(X, (__half*)pXh, W1, (__half*)pW1T, W2, (__half*)pW2T,
                                      (float*)pHS);
    // 2) H1 = X @ W1 + b1          (f16 out)
    gemm_f16_kernel<0><<<dim3(HID / BN, NROWS / BM), 128, SMEM_BYTES>>>(
        (const __half*)pXh, (const __half*)pW1T, b1, pH1, nullptr, nullptr, DIN, DIN / BK);
    // 3) fused: relu(H1 @ W2 + b2) -> head partials into g_HS
    gemm_f16_kernel<1><<<dim3(HID / BN, NROWS / BM), 128, SMEM_BYTES>>>(
        (const __half*)pH1, (const __half*)pW2T, b2, pHS, Wc, Wr, HID, HID / BK);
    // 4) finalize: bias + softmax + boxes
    finalize_kernel<<<NROWS / 256, 256>>>((const float*)pHS, bc, br, out);
}

// round 14
// speedup vs baseline: 1.2756x; 1.1052x over previous
#include <cuda_runtime.h>
#include <cuda_fp16.h>
#include <cstdint>

// ---------------- problem constants ----------------
#define NROWS 8192
#define DIN   12544
#define HID   1024

// ---------------- GEMM tile config: 128x128 tile, 4 warps (64x64 warp tile) ----------------
#define BM 128
#define BN 128
#define BK 64
#define ROWB 144                           // 128B data + 16B pad (conflict-free ldmatrix)
#define STAGE_BYTES ((BM + BN) * ROWB)     // 36864
#define SMEM_BYTES (3 * STAGE_BYTES)       // 110592 -> 2 CTAs/SM

// fused-epilogue smem layout (within the same dynamic smem, after mainloop)
#define TILE_PITCH 264                     // 128 halfs (256B) + 8B pad
#define WSM_OFF    34048                   // 128*264 = 33792, rounded up

// in-GEMM1 conversion: prep pre-converts m-tiles 0..27 (rows < 3584);
// 72 converter CTAs (2 per m-tile) handle m-tiles 28..63.
#define NCONV      72
#define PRECONV_MT 28
#define WAVE1_G    (PRECONV_MT * 8)        // 224 gemm tiles safe in wave 1

// prep kernel sections
#define CONV_BLOCKS 21952                  // 3584*12544/8/256
#define W1T_BX 32
#define W1T_BLOCKS (W1T_BX * (DIN / 32))   // 12544
#define W2T_BX 32
#define W2T_BLOCKS (W2T_BX * (HID / 32))   // 1024
#define ZERO_BLOCKS 128                    // g_HS: 8192*16 f32
#define PREP_BLOCKS (CONV_BLOCKS + W1T_BLOCKS + W2T_BLOCKS + ZERO_BLOCKS + 1)

// ---------------- device scratch ----------------
__device__ __align__(256) __half g_Xh [(size_t)NROWS * DIN];
__device__ __align__(256) __half g_W1T[(size_t)HID * DIN];
__device__ __align__(256) __half g_W2T[(size_t)HID * HID];
__device__ __align__(256) __half g_H1 [(size_t)NROWS * HID];
__device__ __align__(256) float  g_HS [(size_t)NROWS * 16];   // head partial sums
__device__ __align__(256) int    g_flags[64];                 // m-tile convert flags

// ---------------- PTX helpers ----------------
__device__ __forceinline__ uint32_t smem_u32(const void* p) {
    uint32_t a;
    asm("{ .reg .u64 t; cvta.to.shared.u64 t, %1; cvt.u32.u64 %0, t; }" : "=r"(a) : "l"(p));
    return a;
}

#define CP_ASYNC16(dst, src) \
    asm volatile("cp.async.cg.shared.global [%0], [%1], 16;" :: "r"(dst), "l"(src) : "memory")
#define CP_ASYNC_COMMIT() asm volatile("cp.async.commit_group;" ::: "memory")
#define CP_ASYNC_WAIT1()  asm volatile("cp.async.wait_group 1;" ::: "memory")

__device__ __forceinline__ void ldm_x4(uint32_t& r0, uint32_t& r1, uint32_t& r2, uint32_t& r3,
                                       uint32_t addr) {
    asm volatile("ldmatrix.sync.aligned.m8n8.x4.shared.b16 {%0,%1,%2,%3}, [%4];"
                 : "=r"(r0), "=r"(r1), "=r"(r2), "=r"(r3) : "r"(addr));
}

__device__ __forceinline__ void mma16816(float* d, const uint32_t* a, const uint32_t* b) {
    asm volatile(
        "mma.sync.aligned.m16n8k16.row.col.f32.f16.f16.f32 "
        "{%0,%1,%2,%3}, {%4,%5,%6,%7}, {%8,%9}, {%0,%1,%2,%3};"
        : "+f"(d[0]), "+f"(d[1]), "+f"(d[2]), "+f"(d[3])
        : "r"(a[0]), "r"(a[1]), "r"(a[2]), "r"(a[3]), "r"(b[0]), "r"(b[1]));
}

// ---------------- prep: partial X convert + W1/W2 transpose + zero HS/flags ----------------
__global__ void __launch_bounds__(256) prep_kernel(const float* __restrict__ X, __half* __restrict__ Xh,
                                                   const float* __restrict__ W1, __half* __restrict__ W1T,
                                                   const float* __restrict__ W2, __half* __restrict__ W2T,
                                                   float* __restrict__ HS, int* __restrict__ flags) {
    __shared__ float tile[32][33];
    const int b   = blockIdx.x;
    const int tid = threadIdx.x;

    if (b < CONV_BLOCKS) {
        // X rows [0, 3584) -> fp16
        size_t i = (size_t)b * 256 + tid;
        const float4* p = reinterpret_cast<const float4*>(X) + i * 2;
        float4 a = p[0], c = p[1];
        __half2 h0 = __floats2half2_rn(a.x, a.y), h1 = __floats2half2_rn(a.z, a.w);
        __half2 h2 = __floats2half2_rn(c.x, c.y), h3 = __floats2half2_rn(c.z, c.w);
        uint4 v;
        v.x = *reinterpret_cast<uint32_t*>(&h0);
        v.y = *reinterpret_cast<uint32_t*>(&h1);
        v.z = *reinterpret_cast<uint32_t*>(&h2);
        v.w = *reinterpret_cast<uint32_t*>(&h3);
        reinterpret_cast<uint4*>(Xh)[i] = v;
        return;
    }
    if (b >= CONV_BLOCKS + W1T_BLOCKS + W2T_BLOCKS) {
        const int zb = b - (CONV_BLOCKS + W1T_BLOCKS + W2T_BLOCKS);
        if (zb < ZERO_BLOCKS) {
            size_t i = (size_t)zb * 256 + tid;
            reinterpret_cast<uint4*>(HS)[i] = make_uint4(0, 0, 0, 0);
        } else if (tid < 64) {
            flags[tid] = 0;
        }
        return;
    }

    const float* in; __half* out; int R, C, idx, bx;
    if (b < CONV_BLOCKS + W1T_BLOCKS) {
        idx = b - CONV_BLOCKS; in = W1; out = W1T; R = DIN; C = HID; bx = W1T_BX;
    } else {
        idx = b - CONV_BLOCKS - W1T_BLOCKS; in = W2; out = W2T; R = HID; C = HID; bx = W2T_BX;
    }
    const int c0 = (idx % bx) * 32, r0 = (idx / bx) * 32;
    const int x = tid & 31, y = tid >> 5;
    #pragma unroll
    for (int j = 0; j < 32; j += 8)
        tile[y + j][x] = in[(size_t)(r0 + y + j) * C + (c0 + x)];
    __syncthreads();
    #pragma unroll
    for (int j = 0; j < 32; j += 8)
        out[(size_t)(c0 + y + j) * R + (r0 + x)] = __float2half_rn(tile[x][y + j]);
}

// ---------------- mma.sync GEMM: 128 threads / 4 warps, warp tile 64x64, 2 CTAs/SM ----------------
// MODE 0 (GEMM1): 1-D grid 584; bids 0..71 convert X m-tiles 28..63 (2 CTAs each);
//                 bids 72.. are tiles g=bid-72 (m=g>>3, n=g&7); g>=224 waits on flag.
//                 Epilogue: +bias, f16 store to H1.
// MODE 1 (GEMM2): 2-D grid; epilogue relu(+bias) -> smem -> head partials -> atomicAdd g_HS.
template<int MODE>
__global__ void __launch_bounds__(128, 2)
gemm_f16_kernel(const __half* __restrict__ A, const __half* __restrict__ B,
                const float* __restrict__ bias, void* __restrict__ Cout,
                const float* __restrict__ WcH, const float* __restrict__ WrH,
                const float* __restrict__ Xf, __half* __restrict__ XhW,
                int* __restrict__ flags,
                int K, int nk) {
    extern __shared__ char smem[];
    const uint32_t sb = smem_u32(smem);
    const int tid  = threadIdx.x;
    const int wid  = tid >> 5, lane = tid & 31;
    const int wm   = wid & 1;
    const int wn   = wid >> 1;

    int m0, n0;
    if (MODE == 0) {
        if (blockIdx.x < NCONV) {
            // ---- converter CTA: 64 rows of X starting at row 3584 + cid*64 ----
            const int cid = blockIdx.x;
            const int mt  = PRECONV_MT + (cid >> 1);
            const size_t elem0 = ((size_t)mt * 128 + (size_t)(cid & 1) * 64) * DIN;
            const float4* src = reinterpret_cast<const float4*>(Xf + elem0);
            uint2* dst = reinterpret_cast<uint2*>(XhW + elem0);
            const int total = 64 * DIN / 4;   // 200704 float4s
            for (int j = tid; j < total; j += 128) {
                float4 v = __ldg(src + j);
                __half2 h0 = __floats2half2_rn(v.x, v.y), h1 = __floats2half2_rn(v.z, v.w);
                uint2 o;
                o.x = *reinterpret_cast<uint32_t*>(&h0);
                o.y = *reinterpret_cast<uint32_t*>(&h1);
                dst[j] = o;
            }
            __threadfence();
            __syncthreads();
            if (tid == 0) atomicAdd(&flags[mt], 1);
            return;
        }
        const int g = blockIdx.x - NCONV;
        m0 = (g >> 3) * BM;
        n0 = (g & 7) * BN;
        if (g >= WAVE1_G) {
            if (tid == 0) {
                while (atomicAdd(&flags[g >> 3], 0) < 2) __nanosleep(200);
            }
            __syncthreads();
        }
    } else {
        m0 = blockIdx.y * BM;
        n0 = blockIdx.x * BN;
    }

    const int cr = tid >> 3;
    const int cc = (tid & 7) * 16;

    const char* gA = reinterpret_cast<const char*>(A) + ((size_t)(m0 + cr) * K) * 2 + cc;
    const char* gB = reinterpret_cast<const char*>(B) + ((size_t)(n0 + cr) * K) * 2 + cc;
    const size_t rstride = (size_t)16 * K * 2;

    auto issue_stage = [&](int kc, int s) {
        const uint32_t abase = sb + s * STAGE_BYTES;
        const uint32_t bbase = abase + BM * ROWB;
        const size_t koff = (size_t)kc * (BK * 2);
        #pragma unroll
        for (int h = 0; h < 8; h++)
            CP_ASYNC16(abase + (cr + h * 16) * ROWB + cc, gA + koff + h * rstride);
        #pragma unroll
        for (int h = 0; h < 8; h++)
            CP_ASYNC16(bbase + (cr + h * 16) * ROWB + cc, gB + koff + h * rstride);
    };

    const int a_row = lane & 15, a_k8 = lane >> 4;
    const int b_row = (lane & 7) + ((lane >> 4) << 3), b_k8 = (lane >> 3) & 1;

    float acc[4][8][4];
    #pragma unroll
    for (int i = 0; i < 4; i++)
        #pragma unroll
        for (int j = 0; j < 8; j++)
            #pragma unroll
            for (int r = 0; r < 4; r++) acc[i][j][r] = 0.f;

    issue_stage(0, 0); CP_ASYNC_COMMIT();
    if (nk > 1) issue_stage(1, 1); CP_ASYNC_COMMIT();

    int s = 0, s2 = 2;
    for (int kc = 0; kc < nk; kc++) {
        CP_ASYNC_WAIT1();
        __syncthreads();

        if (kc + 2 < nk) issue_stage(kc + 2, s2);
        CP_ASYNC_COMMIT();

        const uint32_t abase = sb + s * STAGE_BYTES;
        const uint32_t bbase = abase + BM * ROWB;

        #pragma unroll
        for (int kk = 0; kk < 4; kk++) {
            uint32_t af[4][4], bf[8][2];
            #pragma unroll
            for (int mi = 0; mi < 4; mi++) {
                uint32_t addr = abase + (wm * 64 + mi * 16 + a_row) * ROWB + (kk * 2 + a_k8) * 16;
                ldm_x4(af[mi][0], af[mi][1], af[mi][2], af[mi][3], addr);
            }
            #pragma unroll
            for (int nb = 0; nb < 4; nb++) {
                uint32_t addr = bbase + (wn * 64 + nb * 16 + b_row) * ROWB + (kk * 2 + b_k8) * 16;
                uint32_t r0, r1, r2, r3;
                ldm_x4(r0, r1, r2, r3, addr);
                bf[nb * 2][0] = r0;     bf[nb * 2][1] = r1;
                bf[nb * 2 + 1][0] = r2; bf[nb * 2 + 1][1] = r3;
            }
            #pragma unroll
            for (int mi = 0; mi < 4; mi++)
                #pragma unroll
                for (int nj = 0; nj < 8; nj++)
                    mma16816(acc[mi][nj], af[mi], bf[nj]);
        }
        s = (s == 2) ? 0 : s + 1;
        s2 = (s2 == 2) ? 0 : s2 + 1;
    }

    const int tq = lane >> 2, tr = lane & 3;

    if (MODE == 0) {
        __half* C = reinterpret_cast<__half*>(Cout);
        #pragma unroll
        for (int nj = 0; nj < 8; nj++) {
            const int col = n0 + wn * 64 + nj * 8 + tr * 2;
            const float bx = bias[col], by = bias[col + 1];
            #pragma unroll
            for (int mi = 0; mi < 4; mi++) {
                const int row = m0 + wm * 64 + mi * 16 + tq;
                __half2 h0 = __floats2half2_rn(acc[mi][nj][0] + bx, acc[mi][nj][1] + by);
                __half2 h1 = __floats2half2_rn(acc[mi][nj][2] + bx, acc[mi][nj][3] + by);
                *reinterpret_cast<__half2*>(C + (size_t)row * HID + col) = h0;
                *reinterpret_cast<__half2*>(C + (size_t)(row + 8) * HID + col) = h1;
            }
        }
        return;
    }

    // ================= MODE 1: fused relu + head partials =================
    __syncthreads();

    #pragma unroll
    for (int nj = 0; nj < 8; nj++) {
        const int coll = wn * 64 + nj * 8 + tr * 2;
        const float bx = bias[n0 + coll], by = bias[n0 + coll + 1];
        #pragma unroll
        for (int mi = 0; mi < 4; mi++) {
            const int rowl = wm * 64 + mi * 16 + tq;
            __half2 h0 = __floats2half2_rn(fmaxf(acc[mi][nj][0] + bx, 0.f),
                                           fmaxf(acc[mi][nj][1] + by, 0.f));
            __half2 h1 = __floats2half2_rn(fmaxf(acc[mi][nj][2] + bx, 0.f),
                                           fmaxf(acc[mi][nj][3] + by, 0.f));
            *reinterpret_cast<__half2*>(smem + rowl * TILE_PITCH + coll * 2) = h0;
            *reinterpret_cast<__half2*>(smem + (rowl + 8) * TILE_PITCH + coll * 2) = h1;
        }
    }

    {
        const int c = tid;
        const int col = n0 + c;
        const float4* Wc4 = reinterpret_cast<const float4*>(WcH);
        const float4* Wr4 = reinterpret_cast<const float4*>(WrH);
        float4* w = reinterpret_cast<float4*>(smem + WSM_OFF + c * 64);
        w[0] = __ldg(Wc4 + col);
        w[1] = __ldg(Wr4 + 3 * col);
        w[2] = __ldg(Wr4 + 3 * col + 1);
        w[3] = __ldg(Wr4 + 3 * col + 2);
    }
    __syncthreads();

    {
        float po[16];
        #pragma unroll
        for (int o = 0; o < 16; o++) po[o] = 0.f;
        const char* trow = smem + tid * TILE_PITCH;
        #pragma unroll 4
        for (int j = 0; j < 32; j++) {
            uint2 hv = *reinterpret_cast<const uint2*>(trow + j * 8);
            const __half2* hp = reinterpret_cast<const __half2*>(&hv);
            float2 f0 = __half22float2(hp[0]), f1 = __half22float2(hp[1]);
            float hvv[4] = { f0.x, f0.y, f1.x, f1.y };
            #pragma unroll
            for (int q = 0; q < 4; q++) {
                const float v = hvv[q];
                const float4* w = reinterpret_cast<const float4*>(smem + WSM_OFF + (4 * j + q) * 64);
                float4 a = w[0], b2 = w[1], c2 = w[2], d = w[3];
                po[0]  += v * a.x;  po[1]  += v * a.y;  po[2]  += v * a.z;  po[3]  += v * a.w;
                po[4]  += v * b2.x; po[5]  += v * b2.y; po[6]  += v * b2.z; po[7]  += v * b2.w;
                po[8]  += v * c2.x; po[9]  += v * c2.y; po[10] += v * c2.z; po[11] += v * c2.w;
                po[12] += v * d.x;  po[13] += v * d.y;  po[14] += v * d.z;  po[15] += v * d.w;
            }
        }
        float* gs = reinterpret_cast<float*>(Cout) + (size_t)(m0 + tid) * 16;
        #pragma unroll
        for (int o = 0; o < 16; o++) atomicAdd(gs + o, po[o]);
    }
}

// ---------------- finalize: bias + softmax + box stores ----------------
__global__ void __launch_bounds__(256) finalize_kernel(const float* __restrict__ HS,
                                                       const float* __restrict__ bc,
                                                       const float* __restrict__ br,
                                                       float* __restrict__ out) {
    const int row = blockIdx.x * 256 + threadIdx.x;
    const float4* p = reinterpret_cast<const float4*>(HS + (size_t)row * 16);
    float4 v0 = p[0], v1 = p[1], v2 = p[2], v3 = p[3];
    float res[16] = { v0.x, v0.y, v0.z, v0.w, v1.x, v1.y, v1.z, v1.w,
                      v2.x, v2.y, v2.z, v2.w, v3.x, v3.y, v3.z, v3.w };
    #pragma unroll
    for (int o = 0; o < 16; o++)
        res[o] += (o < 4) ? __ldg(&bc[o]) : __ldg(&br[o - 4]);
    float m = fmaxf(fmaxf(res[0], res[1]), fmaxf(res[2], res[3]));
    float e0 = expf(res[0] - m), e1 = expf(res[1] - m), e2 = expf(res[2] - m), e3 = expf(res[3] - m);
    float inv = 1.f / (e0 + e1 + e2 + e3);
    out[(size_t)row * 4 + 0] = e0 * inv;
    out[(size_t)row * 4 + 1] = e1 * inv;
    out[(size_t)row * 4 + 2] = e2 * inv;
    out[(size_t)row * 4 + 3] = e3 * inv;
    float* box = out + (size_t)NROWS * 4 + (size_t)row * 12;
    #pragma unroll
    for (int o = 0; o < 12; o++) box[o] = res[o + 4];
}

// ---------------- launch (single stream, serial) ----------------
extern "C" void kernel_launch(void* const* d_in, const int* in_sizes, int n_in,
                              void* d_out, int out_size) {
    (void)in_sizes; (void)n_in; (void)out_size;
    const float* X  = (const float*)d_in[0];
    const float* W1 = (const float*)d_in[1];
    const float* b1 = (const float*)d_in[2];
    const float* W2 = (const float*)d_in[3];
    const float* b2 = (const float*)d_in[4];
    const float* Wc = (const float*)d_in[5];
    const float* bc = (const float*)d_in[6];
    const float* Wr = (const float*)d_in[7];
    const float* br = (const float*)d_in[8];
    float* out = (float*)d_out;

    void *pXh, *pW1T, *pW2T, *pH1, *pHS, *pFlags;
    cudaGetSymbolAddress(&pXh,    g_Xh);
    cudaGetSymbolAddress(&pW1T,   g_W1T);
    cudaGetSymbolAddress(&pW2T,   g_W2T);
    cudaGetSymbolAddress(&pH1,    g_H1);
    cudaGetSymbolAddress(&pHS,    g_HS);
    cudaGetSymbolAddress(&pFlags, g_flags);

    cudaFuncSetAttribute(gemm_f16_kernel<0>, cudaFuncAttributeMaxDynamicSharedMemorySize, SMEM_BYTES);
    cudaFuncSetAttribute(gemm_f16_kernel<1>, cudaFuncAttributeMaxDynamicSharedMemorySize, SMEM_BYTES);

    // 1) prep: X rows [0,3584) -> fp16, W1/W2 transposed f16, zero HS + flags
    prep_kernel<<<PREP_BLOCKS, 256>>>(X, (__half*)pXh, W1, (__half*)pW1T, W2, (__half*)pW2T,
                                      (float*)pHS, (int*)pFlags);
    // 2) GEMM1 (1-D grid: 72 converters + 512 tiles): H1 = X @ W1 + b1
    gemm_f16_kernel<0><<<NCONV + 512, 128, SMEM_BYTES>>>(
        (const __half*)pXh, (const __half*)pW1T, b1, pH1, nullptr, nullptr,
        X, (__half*)pXh, (int*)pFlags, DIN, DIN / BK);
    // 3) fused GEMM2: relu(H1 @ W2 + b2) -> head partials into g_HS
    gemm_f16_kernel<1><<<dim3(HID / BN, NROWS / BM), 128, SMEM_BYTES>>>(
        (const __half*)pH1, (const __half*)pW2T, b2, pHS, Wc, Wr,
        nullptr, nullptr, nullptr, HID, HID / BK);
    // 4) finalize: bias + softmax + boxes
    finalize_kernel<<<NROWS / 256, 256>>>((const float*)pHS, bc, br, out);
}